// round 8
// baseline (speedup 1.0000x reference)
#include <cuda_runtime.h>
#include <cstdint>

#define DD 20
#define NBLK 592

typedef unsigned long long u64;

// ---- packed f32x2 helpers (ptxas won't auto-fuse; must be PTX) ----
__device__ __forceinline__ u64 pk2(float lo, float hi) {
    u64 r; asm("mov.b64 %0, {%1, %2};" : "=l"(r) : "f"(lo), "f"(hi)); return r;
}
__device__ __forceinline__ void upk2(u64 v, float& lo, float& hi) {
    asm("mov.b64 {%0, %1}, %2;" : "=f"(lo), "=f"(hi) : "l"(v));
}
__device__ __forceinline__ u64 fma2(u64 a, u64 b, u64 c) {
    u64 d; asm("fma.rn.f32x2 %0, %1, %2, %3;" : "=l"(d) : "l"(a), "l"(b), "l"(c)); return d;
}
__device__ __forceinline__ u64 add2(u64 a, u64 b) {
    u64 d; asm("add.rn.f32x2 %0, %1, %2;" : "=l"(d) : "l"(a), "l"(b)); return d;
}

// Folded GEMM1 weights, packed f32x2: M[k][p] covers output cols 4p..4p+3; c likewise.
struct CPack {
    ulonglong2 M[DD][5];
    ulonglong2 c[5];
};
__constant__ CPack cpk;      // read by main kernel via constant port
__device__ CPack g_stage;    // written by fold_kernel, memcpy'd into cpk

// block partials: (signed_sum, abs_sum) + completion ticket
__device__ double2 g_part[1024];
__device__ unsigned int g_done = 0;

// ---- fold kernel: M = W^T @ Wi, c = b @ Wi + 1, packed into g_stage ----
__global__ void fold_kernel(const float* __restrict__ W,
                            const float* __restrict__ b,
                            const float* __restrict__ Wi)
{
    __shared__ float sW[DD * DD];
    __shared__ float sWi[DD * DD];
    __shared__ float sb[DD];
    __shared__ float fM[DD * DD];
    __shared__ float fC[DD];

    const int t = threadIdx.x;
    for (int i = t; i < DD * DD; i += 128) { sW[i] = W[i]; sWi[i] = Wi[i]; }
    if (t < DD) sb[t] = b[t];
    __syncthreads();

    for (int i = t; i < DD * DD; i += 128) {
        int k = i / DD, l = i % DD;
        float acc = 0.f;
        #pragma unroll
        for (int j = 0; j < DD; j++) acc += sW[j * DD + k] * sWi[j * DD + l];
        fM[i] = acc;
    }
    if (t < DD) {
        float acc = 1.0f;
        #pragma unroll
        for (int j = 0; j < DD; j++) acc += sb[j] * sWi[j * DD + t];
        fC[t] = acc;
    }
    __syncthreads();

    if (t < DD * 5) {
        int k = t / 5, p = t % 5;
        g_stage.M[k][p].x = pk2(fM[k * DD + 4 * p + 0], fM[k * DD + 4 * p + 1]);
        g_stage.M[k][p].y = pk2(fM[k * DD + 4 * p + 2], fM[k * DD + 4 * p + 3]);
    }
    if (t < 5) {
        g_stage.c[t].x = pk2(fC[4 * t + 0], fC[4 * t + 1]);
        g_stage.c[t].y = pk2(fC[4 * t + 2], fC[4 * t + 3]);
    }
}

__global__ __launch_bounds__(256, 4)
void mm_fused_kernel(const float* __restrict__ X,
                     const float* __restrict__ W,
                     const float* __restrict__ b,
                     float* __restrict__ out,
                     int B)
{
    __shared__ __align__(16) ulonglong2 sWp[DD][5];  // W[*][l] pairs along output cols
    __shared__ __align__(16) ulonglong2 sbp[5];      // b pairs
    __shared__ float sWs[DD * DD];
    __shared__ float sbs[DD];
    __shared__ double sred[16];
    __shared__ bool s_last;

    const int t = threadIdx.x;

    // stage GEMM2 weights into smem (coalesced), then pack
    for (int i = t; i < DD * DD; i += 256) sWs[i] = W[i];
    if (t < DD) sbs[t] = b[t];
    __syncthreads();
    if (t < DD * 5) {
        int l = t / 5, p = t % 5;
        sWp[l][p].x = pk2(sWs[(4 * p + 0) * DD + l], sWs[(4 * p + 1) * DD + l]);
        sWp[l][p].y = pk2(sWs[(4 * p + 2) * DD + l], sWs[(4 * p + 3) * DD + l]);
    }
    if (t < 5) {
        sbp[t].x = pk2(sbs[4 * t + 0], sbs[4 * t + 1]);
        sbp[t].y = pk2(sbs[4 * t + 2], sbs[4 * t + 3]);
    }
    __syncthreads();

    const u64 AMASK = 0x7FFFFFFF7FFFFFFFULL;
    u64 sv = 0ULL, sa = 0ULL;  // packed accumulators

    const int stride = NBLK * 256;
    for (int row = blockIdx.x * 256 + t; row < B; row += stride) {
        const float4* xr = reinterpret_cast<const float4*>(X) + (size_t)row * 5;
        float xs[DD];
        #pragma unroll
        for (int i = 0; i < 5; i++) {
            float4 v = __ldg(xr + i);
            xs[4 * i + 0] = v.x; xs[4 * i + 1] = v.y;
            xs[4 * i + 2] = v.z; xs[4 * i + 3] = v.w;
        }

        // GEMM1: y = X@M + c  — weights from CONSTANT port, off the crossbar
        u64 y[10];
        #pragma unroll
        for (int p = 0; p < 5; p++) {
            ulonglong2 cc = cpk.c[p];
            y[2 * p] = cc.x; y[2 * p + 1] = cc.y;
        }
        #pragma unroll
        for (int k = 0; k < DD; k++) {
            u64 xk = pk2(xs[k], xs[k]);
            #pragma unroll
            for (int p = 0; p < 5; p++) {
                ulonglong2 m = cpk.M[k][p];
                y[2 * p]     = fma2(xk, m.x, y[2 * p]);
                y[2 * p + 1] = fma2(xk, m.y, y[2 * p + 1]);
            }
        }

        // h = relu(y), stored back into xs (xs dead after GEMM1)
        #pragma unroll
        for (int j = 0; j < 10; j++) {
            float lo, hi; upk2(y[j], lo, hi);
            xs[2 * j]     = fmaxf(lo, 0.f);
            xs[2 * j + 1] = fmaxf(hi, 0.f);
        }

        // GEMM2: a = h @ W^T + b — weights from SMEM broadcast (LDS.128), reuse y as accum
        #pragma unroll
        for (int p = 0; p < 5; p++) {
            ulonglong2 bb = sbp[p];
            y[2 * p] = bb.x; y[2 * p + 1] = bb.y;
        }
        #pragma unroll
        for (int l = 0; l < DD; l++) {
            u64 hl = pk2(xs[l], xs[l]);
            #pragma unroll
            for (int p = 0; p < 5; p++) {
                ulonglong2 w = sWp[l][p];
                y[2 * p]     = fma2(hl, w.x, y[2 * p]);
                y[2 * p + 1] = fma2(hl, w.y, y[2 * p + 1]);
            }
        }

        // accumulate signed + abs sums (packed)
        u64 rs = y[0];
        u64 ra = y[0] & AMASK;
        #pragma unroll
        for (int j = 1; j < 10; j++) {
            rs = add2(rs, y[j]);
            ra = add2(ra, y[j] & AMASK);
        }
        sv = add2(sv, rs);
        sa = add2(sa, ra);
    }

    // deterministic reduction: thread -> warp -> block
    float slo, shi, alo, ahi;
    upk2(sv, slo, shi); upk2(sa, alo, ahi);
    double ds = (double)slo + (double)shi;
    double da = (double)alo + (double)ahi;
    #pragma unroll
    for (int o = 16; o > 0; o >>= 1) {
        ds += __shfl_down_sync(0xFFFFFFFFu, ds, o);
        da += __shfl_down_sync(0xFFFFFFFFu, da, o);
    }
    const int wid = t >> 5, lid = t & 31;
    if (lid == 0) { sred[wid] = ds; sred[8 + wid] = da; }
    __syncthreads();
    if (t == 0) {
        double S = 0.0, A = 0.0;
        #pragma unroll
        for (int w = 0; w < 8; w++) { S += sred[w]; A += sred[8 + w]; }
        g_part[blockIdx.x] = make_double2(S, A);
        __threadfence();
        unsigned int prev = atomicAdd(&g_done, 1u);
        s_last = (prev == NBLK - 1);
    }
    __syncthreads();

    // last block performs the final reduction (deterministic fixed order)
    if (s_last) {
        __threadfence();  // acquire partials
        double S = 0.0, A = 0.0;
        for (int i = t; i < NBLK; i += 256) {
            double2 p = g_part[i];
            S += p.x; A += p.y;
        }
        #pragma unroll
        for (int o = 16; o > 0; o >>= 1) {
            S += __shfl_down_sync(0xFFFFFFFFu, S, o);
            A += __shfl_down_sync(0xFFFFFFFFu, A, o);
        }
        __syncthreads();   // sred reuse
        if (lid == 0) { sred[wid] = S; sred[8 + wid] = A; }
        __syncthreads();
        if (t == 0) {
            double St = 0.0, At = 0.0;
            #pragma unroll
            for (int w = 0; w < 8; w++) { St += sred[w]; At += sred[8 + w]; }
            int k = 0;
            double s = At;
            while (s > 1.0 && k < 4000) { s *= 0.5; k++; }
            out[0] = (float)ldexp(St, -k);
            g_done = 0;  // reset ticket for next graph replay
        }
    }
}

extern "C" void kernel_launch(void* const* d_in, const int* in_sizes, int n_in,
                              void* d_out, int out_size)
{
    const float* X  = (const float*)d_in[0];
    const float* W  = (const float*)d_in[1];
    const float* b  = (const float*)d_in[2];
    const float* Wi = (const float*)d_in[3];
    float* out = (float*)d_out;

    const int B = in_sizes[0] / DD;

    // 1) fold weights into staging
    fold_kernel<<<1, 128>>>(W, b, Wi);

    // 2) staging -> __constant__ (graph-legal async D2D copy)
    void* dst = nullptr;
    void* src = nullptr;
    cudaGetSymbolAddress(&dst, cpk);
    cudaGetSymbolAddress(&src, g_stage);
    cudaMemcpyAsync(dst, src, sizeof(CPack), cudaMemcpyDeviceToDevice, 0);

    // 3) main fused pass (occ 4: 32 warps/SM)
    mm_fused_kernel<<<NBLK, 256>>>(X, W, b, out, B);
}